// round 4
// baseline (speedup 1.0000x reference)
#include <cuda_runtime.h>
#include <cstdint>
#include <cstddef>

using ull = unsigned long long;

#define THREADS 288
#define NCH     256
#define CK      8
#define NSTAGE  (NCH / CK)
#define H       64
#define W       64
#define TH      16
#define TW      32
#define YROWS   (TH + 8)     // 24
#define YSTR    44           // padded row stride (floats) -> conflict-free LDS.128
#define XSTR    36           // padded row stride (floats) -> conflict-free LDS.128
#define YS_BUF  (CK * YROWS * YSTR)   // 8448 floats per buffer
#define XS_BUF  (CK * TH * XSTR)      // 4608 floats per buffer
#define SMEM_FLOATS (2 * YS_BUF + 2 * XS_BUF)   // 26112
#define SMEM_BYTES  (SMEM_FLOATS * 4)           // 104448

// ---- async copy helpers (zfill handles the zero-padded halo) ----
__device__ __forceinline__ void cp16(uint32_t dst, const float* src, int ok) {
    asm volatile("cp.async.cg.shared.global [%0], [%1], 16, %2;\n"
                 :: "r"(dst), "l"(src), "r"(ok ? 16 : 0));
}
__device__ __forceinline__ void cp_commit() { asm volatile("cp.async.commit_group;\n"); }
__device__ __forceinline__ void cp_wait0()  { asm volatile("cp.async.wait_group 0;\n"); }

// ---- packed f32x2 math (FFMA2: 2x fp32 rate, PTX-only per sm_103a SASS notes) ----
__device__ __forceinline__ void fma2(ull& acc, ull a, ull b) {
    asm("fma.rn.f32x2 %0, %1, %2, %0;" : "+l"(acc) : "l"(a), "l"(b));
}
__device__ __forceinline__ ull mul2(ull a, ull b) {
    ull d;
    asm("mul.rn.f32x2 %0, %1, %2;" : "=l"(d) : "l"(a), "l"(b));
    return d;
}

__global__ __launch_bounds__(THREADS, 1)
void corr_kernel(const float* __restrict__ xg, const float* __restrict__ yg,
                 float* __restrict__ out) {
    extern __shared__ float sm[];

    const int tid  = threadIdx.x;
    const int bb   = blockIdx.x >> 3;          // batch
    const int tile = blockIdx.x & 7;           // 4 row-tiles x 2 col-tiles
    const int i0   = (tile >> 1) * TH;
    const int j0   = (tile & 1) * TW;

    const int di   = tid >> 5;                 // warp id = vertical displacement 0..8
    const int lane = tid & 31;
    const int gi   = lane >> 1;                // pixel row within tile 0..15
    const int jl   = (lane & 1) * 16;          // pixel col group start: 0 or 16

    const uint32_t sbase = (uint32_t)__cvta_generic_to_shared(sm);

    // 72 packed accumulators: acc[dj*8 + m] holds pixels (2m, 2m+1) for this di, dj
    ull acc[72];
#pragma unroll
    for (int k = 0; k < 72; k++) acc[k] = 0ULL;

    // ---------------- stage loader (cp.async into buffer 'buf') ----------------
    auto load_stage = [&](int s, int buf) {
        const int c0 = s * CK;
        const uint32_t ybase = sbase + (uint32_t)(buf * YS_BUF) * 4u;
#pragma unroll 1
        for (int idx = tid; idx < CK * YROWS * 10; idx += THREADS) {
            int cc  = idx / (YROWS * 10);
            int rem = idx - cc * (YROWS * 10);
            int r   = rem / 10;
            int q   = rem - r * 10;
            int gr  = i0 + r - 4;
            int gc  = j0 - 4 + 4 * q;
            int ok  = (gr >= 0) & (gr < H) & (gc >= 0) & (gc < W);
            const float* src = yg + (((size_t)(bb * NCH + c0 + cc) * H + (ok ? gr : 0)) * W
                                     + (ok ? gc : 0));
            uint32_t dst = ybase + (uint32_t)(((cc * YROWS + r) * YSTR + 4 * q)) * 4u;
            cp16(dst, src, ok);
        }
        const uint32_t xbase = sbase + (uint32_t)(2 * YS_BUF + buf * XS_BUF) * 4u;
#pragma unroll 1
        for (int idx = tid; idx < CK * TH * 8; idx += THREADS) {
            int cc  = idx / (TH * 8);
            int rem = idx - cc * (TH * 8);
            int r   = rem >> 3;
            int q   = rem & 7;
            const float* src = xg + (((size_t)(bb * NCH + c0 + cc) * H + (i0 + r)) * W
                                     + (j0 + 4 * q));
            uint32_t dst = xbase + (uint32_t)((cc * TH + r) * XSTR + 4 * q) * 4u;
            cp16(dst, src, 1);
        }
        cp_commit();
    };

    // ---------------- pipeline ----------------
    load_stage(0, 0);
    cp_wait0();
    __syncthreads();

#pragma unroll 1
    for (int s = 0; s < NSTAGE; s++) {
        const int buf = s & 1;
        if (s + 1 < NSTAGE) load_stage(s + 1, buf ^ 1);

        const float* ysb = sm + buf * YS_BUF;
        const float* xsb = sm + 2 * YS_BUF + buf * XS_BUF;

#pragma unroll
        for (int cc = 0; cc < CK; cc++) {
            const ulonglong2* xr =
                (const ulonglong2*)(xsb + (cc * TH + gi) * XSTR + jl);
            const ulonglong2* yr =
                (const ulonglong2*)(ysb + (cc * YROWS + gi + di) * YSTR + jl);

            ull xp[8];
#pragma unroll
            for (int k = 0; k < 4; k++) {
                ulonglong2 u = xr[k];
                xp[2 * k] = u.x; xp[2 * k + 1] = u.y;
            }
            ull w[12];
#pragma unroll
            for (int k = 0; k < 6; k++) {
                ulonglong2 u = yr[k];
                w[2 * k] = u.x; w[2 * k + 1] = u.y;
            }
            // shifted (odd-offset) pairs: sp[q] = { y[2q+1], y[2q+2] }
            ull sp[11];
#pragma unroll
            for (int q = 0; q < 11; q++) sp[q] = (w[q] >> 32) | (w[q + 1] << 32);

#pragma unroll
            for (int dj = 0; dj < 9; dj++) {
#pragma unroll
                for (int m = 0; m < 8; m++) {
                    const int o = 2 * m + dj;   // compile-time
                    fma2(acc[dj * 8 + m], xp[m], (o & 1) ? sp[o >> 1] : w[o >> 1]);
                }
            }
        }

        cp_wait0();        // stage s+1 landed
        __syncthreads();   // everyone done reading buf before it is overwritten
    }

    // ---------------- epilogue: scale by 1/C and store ----------------
    const uint32_t su = __float_as_uint(1.0f / 256.0f);
    const ull scl = ((ull)su << 32) | su;
#pragma unroll
    for (int dj = 0; dj < 9; dj++) {
        float* op = out + (((size_t)bb * 81 + di * 9 + dj) * H + (i0 + gi)) * W
                        + j0 + jl;
        ulonglong2* ov = (ulonglong2*)op;
#pragma unroll
        for (int k = 0; k < 4; k++) {
            ulonglong2 v;
            v.x = mul2(acc[dj * 8 + 2 * k], scl);
            v.y = mul2(acc[dj * 8 + 2 * k + 1], scl);
            ov[k] = v;
        }
    }
}

extern "C" void kernel_launch(void* const* d_in, const int* in_sizes, int n_in,
                              void* d_out, int out_size) {
    (void)in_sizes; (void)n_in; (void)out_size;
    const float* x = (const float*)d_in[0];
    const float* y = (const float*)d_in[1];
    cudaFuncSetAttribute(corr_kernel, cudaFuncAttributeMaxDynamicSharedMemorySize,
                         SMEM_BYTES);
    corr_kernel<<<16 * 8, THREADS, SMEM_BYTES>>>(x, y, (float*)d_out);
}